// round 10
// baseline (speedup 1.0000x reference)
#include <cuda_runtime.h>
#include <cstdint>

#define Bn   4096
#define Tn   64
#define DIN  300
#define Hn   3
#define DIN4 75      // 300/4
#define C2LE 2.885390081777927f   // 2*log2(e): folded into xb and W_hh

// xb in padded [t][b][4] layout, PRE-SCALED by 2*log2(e).
__device__ float g_xb[(size_t)Tn * Bn * 4];   // 4 MB

__device__ __forceinline__ int detect_is64(const void* L) {
    return ((const int*)L)[1] == 0;
}
__device__ __forceinline__ int length_at(const void* L, int b, int is64) {
    if (is64) return (int)((const long long*)L)[b];
    return ((const int*)L)[b];
}

__device__ __forceinline__ uint32_t smem_u32(const void* p) {
    uint32_t a;
    asm("{ .reg .u64 t; cvta.to.shared.u64 t, %1; cvt.u32.u64 %0, t; }"
        : "=r"(a) : "l"(p));
    return a;
}

__device__ __forceinline__ float tanh_pre(float a) {
    float e, r;
    asm("ex2.approx.f32 %0, %1;" : "=f"(e) : "f"(a));
    asm("rcp.approx.f32 %0, %1;" : "=f"(r) : "f"(e + 1.0f));
    return fmaf(-2.0f, r, 1.0f);
}

// packed f32x2 helpers
__device__ __forceinline__ unsigned long long pk2(float lo, float hi) {
    unsigned long long r;
    asm("mov.b64 %0, {%1, %2};" : "=l"(r) : "f"(lo), "f"(hi));
    return r;
}
__device__ __forceinline__ void unpk2(unsigned long long p, float& lo, float& hi) {
    asm("mov.b64 {%0, %1}, %2;" : "=f"(lo), "=f"(hi) : "l"(p));
}
__device__ __forceinline__ unsigned long long fma2(
    unsigned long long a, unsigned long long b, unsigned long long c) {
    unsigned long long d;
    asm("fma.rn.f32x2 %0, %1, %2, %3;" : "=l"(d) : "l"(a), "l"(b), "l"(c));
    return d;
}

// ---------------------------------------------------------------------------
// Phase 1: xb[t][b][.] = (x[b,t,:].W_ih[h,:] + b_ih[h] + b_hh[h]) * 2log2e
// One warp = 4 consecutive timesteps of one sample.
//  - cp.async stages the 4 rows into smem (fire-and-forget: no live v regs,
//    each lane reads back exactly the slots it wrote -> wait_group suffices)
//  - x loads tagged L2::evict_first (zero reuse; stop thrashing xb out of L2)
//  - dot products in packed fma.rn.f32x2 (half the FMA issue)
//  - xb stores tagged L2::evict_last (keep resident for k_rnn)
// ---------------------------------------------------------------------------
__global__ __launch_bounds__(256, 3) void k_proj(
    const float* __restrict__ x,
    const void*  __restrict__ L,
    const float* __restrict__ W_ih,
    const float* __restrict__ b_ih,
    const float* __restrict__ b_hh)
{
    __shared__ float4 tile[8][4 * DIN4];   // 38400 B: [warp][r*75 + j]

    const int gw   = (blockIdx.x * blockDim.x + threadIdx.x) >> 5;
    const int wid  = (threadIdx.x >> 5);
    const int lane = threadIdx.x & 31;
    const int b     = gw >> 4;
    const int tbase = (gw & 15) << 2;

    const int is64 = detect_is64(L);
    const int len  = length_at(L, b, is64);
    if (tbase >= len) return;                       // dead group: no traffic
    const int nrows = (len - tbase < 4) ? (len - tbase) : 4;

    unsigned long long pol_first, pol_last;
    asm("createpolicy.fractional.L2::evict_first.b64 %0, 1.0;" : "=l"(pol_first));
    asm("createpolicy.fractional.L2::evict_last.b64 %0, 1.0;"  : "=l"(pol_last));

    // ---- issue all 12 cp.async (4 rows x 3 waves); k=2 wave only lanes<11 ----
    const float4* __restrict__ xr = (const float4*)x + (size_t)(b * Tn + tbase) * DIN4;
    {
        const uint32_t ts = smem_u32(&tile[wid][0]);
        #pragma unroll
        for (int r = 0; r < 4; ++r) {
            #pragma unroll
            for (int k = 0; k < 3; ++k) {
                const int j = lane + 32 * k;
                if (k < 2 || lane < 11) {
                    asm volatile(
                        "cp.async.cg.shared.global.L2::cache_hint [%0], [%1], 16, %2;"
                        :: "r"(ts + (uint32_t)(r * DIN4 + j) * 16),
                           "l"(xr + r * DIN4 + j), "l"(pol_first) : "memory");
                }
            }
        }
        asm volatile("cp.async.commit_group;" ::: "memory");
    }

    // ---- while loads fly: pack weights into b64 registers ----
    const float4* __restrict__ W4 = (const float4*)W_ih;
    unsigned long long wlo[Hn][3], whi[Hn][3];
    #pragma unroll
    for (int h = 0; h < Hn; ++h)
        #pragma unroll
        for (int k = 0; k < 3; ++k) {
            const int j = lane + 32 * k;
            float4 wv = (j < DIN4) ? W4[h * DIN4 + j] : make_float4(0.f,0.f,0.f,0.f);
            wlo[h][k] = pk2(wv.x, wv.y);
            whi[h][k] = pk2(wv.z, wv.w);
        }

    const float bs0 = b_ih[0] + b_hh[0];
    const float bs1 = b_ih[1] + b_hh[1];
    const float bs2 = b_ih[2] + b_hh[2];

    asm volatile("cp.async.wait_group 0;" ::: "memory");
    __syncwarp();

    // ---- packed dot products: 72 fma.f32x2 per lane ----
    unsigned long long acc[4][Hn];
    #pragma unroll
    for (int r = 0; r < 4; ++r)
        #pragma unroll
        for (int h = 0; h < Hn; ++h) acc[r][h] = pk2(0.f, 0.f);

    #pragma unroll
    for (int k = 0; k < 3; ++k) {
        if (k < 2 || lane < 11) {
            const int j = lane + 32 * k;
            #pragma unroll
            for (int r = 0; r < 4; ++r) {
                const ulonglong2 u =
                    *(const ulonglong2*)&tile[wid][r * DIN4 + j];   // LDS.128
                #pragma unroll
                for (int h = 0; h < Hn; ++h) {
                    acc[r][h] = fma2(u.x, wlo[h][k], acc[r][h]);
                    acc[r][h] = fma2(u.y, whi[h][k], acc[r][h]);
                }
            }
        }
    }

    // ---- horizontal: unpack-add then 12 pipelined 5-level butterflies ----
    float a[4][Hn];
    #pragma unroll
    for (int r = 0; r < 4; ++r)
        #pragma unroll
        for (int h = 0; h < Hn; ++h) {
            float lo, hi;
            unpk2(acc[r][h], lo, hi);
            a[r][h] = lo + hi;
        }
    #pragma unroll
    for (int r = 0; r < 4; ++r)
        #pragma unroll
        for (int off = 16; off; off >>= 1) {
            a[r][0] += __shfl_xor_sync(0xffffffffu, a[r][0], off);
            a[r][1] += __shfl_xor_sync(0xffffffffu, a[r][1], off);
            a[r][2] += __shfl_xor_sync(0xffffffffu, a[r][2], off);
        }

    if (lane == 0) {
        #pragma unroll
        for (int r = 0; r < 4; ++r) {
            if (r < nrows) {
                const float ox = (a[r][0] + bs0) * C2LE;
                const float oy = (a[r][1] + bs1) * C2LE;
                const float oz = (a[r][2] + bs2) * C2LE;
                float* ptr = g_xb + ((size_t)(tbase + r) * Bn + b) * 4;
                asm volatile(
                    "st.global.L2::cache_hint.v4.f32 [%0], {%1,%2,%3,%4}, %5;"
                    :: "l"(ptr), "f"(ox), "f"(oy), "f"(oz), "f"(0.f),
                       "l"(pol_last) : "memory");
            }
        }
    }
}

// ---------------------------------------------------------------------------
// Phase 2: branchless sequential recurrence (unchanged from best-measured).
// xb should now be L2-resident thanks to the eviction policies above.
// ---------------------------------------------------------------------------
__global__ __launch_bounds__(32) void k_rnn(
    const void*  __restrict__ L,
    const float* __restrict__ W_hh,
    float*       __restrict__ out)
{
    __shared__ float4 buf[Tn][32];     // 32 KB
    const int tid = threadIdx.x;
    const int b   = blockIdx.x * 32 + tid;
    const int is64 = detect_is64(L);
    const int len  = length_at(L, b, is64);   // >= 1

    const float4* __restrict__ p = (const float4*)g_xb;

    #pragma unroll
    for (int g = 0; g < 4; ++g) {
        #pragma unroll
        for (int tl = 0; tl < 16; ++tl) {
            const int t = g * 16 + tl;
            const uint32_t d = smem_u32(&buf[t][tid]);
            const float4* s = p + (size_t)t * Bn + b;
            asm volatile("cp.async.cg.shared.global [%0], [%1], 16;"
                         :: "r"(d), "l"(s) : "memory");
        }
        asm volatile("cp.async.commit_group;" ::: "memory");
    }

    const float w00 = W_hh[0]*C2LE, w01 = W_hh[1]*C2LE, w02 = W_hh[2]*C2LE;
    const float w10 = W_hh[3]*C2LE, w11 = W_hh[4]*C2LE, w12 = W_hh[5]*C2LE;
    const float w20 = W_hh[6]*C2LE, w21 = W_hh[7]*C2LE, w22 = W_hh[8]*C2LE;

    float h0 = 0.f, h1 = 0.f, h2 = 0.f;

    asm volatile("cp.async.wait_group 3;" ::: "memory");
    float4 cur = buf[0][tid];
    float4 nxt = buf[1][tid];

    #define STEP(T) do {                                                      \
        const float x0 = cur.x, x1 = cur.y, x2 = cur.z;                       \
        cur = nxt;                                                            \
        if ((T) + 2 < Tn) nxt = buf[(T) + 2][tid];                            \
        const float a0 = x0 + h0*w00 + h1*w01 + h2*w02;                       \
        const float a1 = x1 + h0*w10 + h1*w11 + h2*w12;                       \
        const float a2 = x2 + h0*w20 + h1*w21 + h2*w22;                       \
        const float t0 = tanh_pre(a0);                                        \
        const float t1 = tanh_pre(a1);                                        \
        const float t2 = tanh_pre(a2);                                        \
        const bool lv = (T) < len;                                            \
        h0 = lv ? t0 : h0;                                                    \
        h1 = lv ? t1 : h1;                                                    \
        h2 = lv ? t2 : h2;                                                    \
    } while (0)
    #define S2(T)  STEP(T); STEP((T)+1)
    #define S8(T)  S2(T); S2((T)+2); S2((T)+4); S2((T)+6)

    S8(0); S2(8); S2(10); S2(12);
    asm volatile("cp.async.wait_group 2;" ::: "memory");
    S2(14); S8(16); S2(24); S2(26); S2(28);
    asm volatile("cp.async.wait_group 1;" ::: "memory");
    S2(30); S8(32); S2(40); S2(42); S2(44);
    asm volatile("cp.async.wait_group 0;" ::: "memory");
    S2(46); S8(48); S8(56);

    #undef S8
    #undef S2
    #undef STEP

    out[b * Hn + 0] = h0;
    out[b * Hn + 1] = h1;
    out[b * Hn + 2] = h2;
}

extern "C" void kernel_launch(void* const* d_in, const int* in_sizes, int n_in,
                              void* d_out, int out_size)
{
    const float* x    = (const float*)d_in[0];
    const void*  L    = d_in[1];
    const float* W_ih = (const float*)d_in[2];
    const float* W_hh = (const float*)d_in[3];
    const float* b_ih = (const float*)d_in[4];
    const float* b_hh = (const float*)d_in[5];
    float* out = (float*)d_out;

    // 65536 warps (4 timesteps each), 8 warps/block -> 8192 blocks
    k_proj<<<8192, 256>>>(x, L, W_ih, b_ih, b_hh);
    k_rnn<<<Bn / 32, 32>>>(L, W_hh, out);
}

// round 12
// speedup vs baseline: 1.1848x; 1.1848x over previous
#include <cuda_runtime.h>
#include <cstdint>

#define Bn   4096
#define Tn   64
#define DIN  300
#define Hn   3
#define DIN4 75      // 300/4
#define C2LE 2.885390081777927f   // 2*log2(e): folded into xb and W_hh

// xb in padded [t][b][4] layout, PRE-SCALED by 2*log2(e).
__device__ float g_xb[(size_t)Tn * Bn * 4];   // 4 MB

__device__ __forceinline__ int detect_is64(const void* L) {
    return ((const int*)L)[1] == 0;
}
__device__ __forceinline__ int length_at(const void* L, int b, int is64) {
    if (is64) return (int)((const long long*)L)[b];
    return ((const int*)L)[b];
}

__device__ __forceinline__ uint32_t smem_u32(const void* p) {
    uint32_t a;
    asm("{ .reg .u64 t; cvta.to.shared.u64 t, %1; cvt.u32.u64 %0, t; }"
        : "=r"(a) : "l"(p));
    return a;
}

// tanh from pre-scaled argument a = 2*log2(e)*x:
//   tanh(x) = 1 - 2/(2^a + 1).  MUFU EX2 + MUFU RCP, few-ulp, saturates right.
__device__ __forceinline__ float tanh_pre(float a) {
    float e, r;
    asm("ex2.approx.f32 %0, %1;" : "=f"(e) : "f"(a));
    asm("rcp.approx.f32 %0, %1;" : "=f"(r) : "f"(e + 1.0f));
    return fmaf(-2.0f, r, 1.0f);
}

// no-op kernel: shifts ncu's capture slot (-s 5 -c 1) onto k_proj.
// Launch order per call is [nop, proj, rnn, nop] -> launch #6 = k_proj.
__global__ void k_nop() {}

// ---------------------------------------------------------------------------
// Phase 1 (exact R8 best-measured): one warp = NR (<=4) consecutive timesteps
// of one sample; two-wave load pipeline, weights in 9 float4 regs/lane,
// NR pipelined shfl reductions.
// ---------------------------------------------------------------------------
template<int NR>
__device__ __forceinline__ void proj_rows(
    const float4* __restrict__ xr,
    const float4 (&w)[Hn][3], int lane,
    float bs0, float bs1, float bs2,
    float4* __restrict__ xb4, int tbase, int b)
{
    const int j0 = lane;
    const int j1 = lane + 32;
    const int j2 = lane + 64;
    const bool p2 = (j2 < DIN4);

    float acc[NR][3];
    #pragma unroll
    for (int r = 0; r < NR; ++r) { acc[r][0]=0.f; acc[r][1]=0.f; acc[r][2]=0.f; }

    float4 v0[NR], v1[NR];
    #pragma unroll
    for (int r = 0; r < NR; ++r) v0[r] = xr[r * DIN4 + j0];
    #pragma unroll
    for (int r = 0; r < NR; ++r) v1[r] = xr[r * DIN4 + j1];

    #pragma unroll
    for (int r = 0; r < NR; ++r) {
        #pragma unroll
        for (int h = 0; h < Hn; ++h)
            acc[r][h] += v0[r].x*w[h][0].x + v0[r].y*w[h][0].y
                       + v0[r].z*w[h][0].z + v0[r].w*w[h][0].w;
    }
    #pragma unroll
    for (int r = 0; r < NR; ++r)
        v0[r] = p2 ? xr[r * DIN4 + j2] : make_float4(0.f,0.f,0.f,0.f);
    #pragma unroll
    for (int r = 0; r < NR; ++r) {
        #pragma unroll
        for (int h = 0; h < Hn; ++h)
            acc[r][h] += v1[r].x*w[h][1].x + v1[r].y*w[h][1].y
                       + v1[r].z*w[h][1].z + v1[r].w*w[h][1].w;
    }
    #pragma unroll
    for (int r = 0; r < NR; ++r) {
        #pragma unroll
        for (int h = 0; h < Hn; ++h)
            acc[r][h] += v0[r].x*w[h][2].x + v0[r].y*w[h][2].y
                       + v0[r].z*w[h][2].z + v0[r].w*w[h][2].w;
    }

    #pragma unroll
    for (int r = 0; r < NR; ++r) {
        #pragma unroll
        for (int off = 16; off; off >>= 1) {
            acc[r][0] += __shfl_xor_sync(0xffffffffu, acc[r][0], off);
            acc[r][1] += __shfl_xor_sync(0xffffffffu, acc[r][1], off);
            acc[r][2] += __shfl_xor_sync(0xffffffffu, acc[r][2], off);
        }
    }

    if (lane == 0) {
        #pragma unroll
        for (int r = 0; r < NR; ++r) {
            float4 o;
            o.x = (acc[r][0] + bs0) * C2LE;
            o.y = (acc[r][1] + bs1) * C2LE;
            o.z = (acc[r][2] + bs2) * C2LE;
            o.w = 0.f;
            xb4[(size_t)(tbase + r) * Bn + b] = o;
        }
    }
}

__global__ __launch_bounds__(256) void k_proj(
    const float* __restrict__ x,
    const void*  __restrict__ L,
    const float* __restrict__ W_ih,
    const float* __restrict__ b_ih,
    const float* __restrict__ b_hh)
{
    const int gw   = (blockIdx.x * blockDim.x + threadIdx.x) >> 5;
    const int lane = threadIdx.x & 31;
    const int b     = gw >> 4;
    const int tbase = (gw & 15) << 2;

    const int is64 = detect_is64(L);
    const int len  = length_at(L, b, is64);
    if (tbase >= len) return;
    const int nrows = (len - tbase < 4) ? (len - tbase) : 4;

    const float4* __restrict__ W4 = (const float4*)W_ih;
    float4 w[Hn][3];
    #pragma unroll
    for (int h = 0; h < Hn; ++h)
        #pragma unroll
        for (int k = 0; k < 3; ++k) {
            const int j = lane + 32 * k;
            w[h][k] = (j < DIN4) ? W4[h * DIN4 + j] : make_float4(0.f,0.f,0.f,0.f);
        }

    const float bs0 = b_ih[0] + b_hh[0];
    const float bs1 = b_ih[1] + b_hh[1];
    const float bs2 = b_ih[2] + b_hh[2];

    const float4* __restrict__ xr = (const float4*)x + (size_t)(b * Tn + tbase) * DIN4;
    float4* __restrict__ xb4 = (float4*)g_xb;

    switch (nrows) {
        case 4: proj_rows<4>(xr, w, lane, bs0, bs1, bs2, xb4, tbase, b); break;
        case 3: proj_rows<3>(xr, w, lane, bs0, bs1, bs2, xb4, tbase, b); break;
        case 2: proj_rows<2>(xr, w, lane, bs0, bs1, bs2, xb4, tbase, b); break;
        default: proj_rows<1>(xr, w, lane, bs0, bs1, bs2, xb4, tbase, b); break;
    }
}

// ---------------------------------------------------------------------------
// Phase 2 (exact R8 best-measured): branchless unrolled recurrence out of
// cp.async-staged shared memory; FSEL freeze mask; compile-time waits.
// ---------------------------------------------------------------------------
__global__ __launch_bounds__(32) void k_rnn(
    const void*  __restrict__ L,
    const float* __restrict__ W_hh,
    float*       __restrict__ out)
{
    __shared__ float4 buf[Tn][32];     // 32 KB
    const int tid = threadIdx.x;
    const int b   = blockIdx.x * 32 + tid;
    const int is64 = detect_is64(L);
    const int len  = length_at(L, b, is64);   // >= 1

    const float4* __restrict__ p = (const float4*)g_xb;

    #pragma unroll
    for (int g = 0; g < 4; ++g) {
        #pragma unroll
        for (int tl = 0; tl < 16; ++tl) {
            const int t = g * 16 + tl;
            const uint32_t d = smem_u32(&buf[t][tid]);
            const float4* s = p + (size_t)t * Bn + b;
            asm volatile("cp.async.cg.shared.global [%0], [%1], 16;"
                         :: "r"(d), "l"(s) : "memory");
        }
        asm volatile("cp.async.commit_group;" ::: "memory");
    }

    const float w00 = W_hh[0]*C2LE, w01 = W_hh[1]*C2LE, w02 = W_hh[2]*C2LE;
    const float w10 = W_hh[3]*C2LE, w11 = W_hh[4]*C2LE, w12 = W_hh[5]*C2LE;
    const float w20 = W_hh[6]*C2LE, w21 = W_hh[7]*C2LE, w22 = W_hh[8]*C2LE;

    float h0 = 0.f, h1 = 0.f, h2 = 0.f;

    asm volatile("cp.async.wait_group 3;" ::: "memory");
    float4 cur = buf[0][tid];
    float4 nxt = buf[1][tid];

    #define STEP(T) do {                                                      \
        const float x0 = cur.x, x1 = cur.y, x2 = cur.z;                       \
        cur = nxt;                                                            \
        if ((T) + 2 < Tn) nxt = buf[(T) + 2][tid];                            \
        const float a0 = x0 + h0*w00 + h1*w01 + h2*w02;                       \
        const float a1 = x1 + h0*w10 + h1*w11 + h2*w12;                       \
        const float a2 = x2 + h0*w20 + h1*w21 + h2*w22;                       \
        const float t0 = tanh_pre(a0);                                        \
        const float t1 = tanh_pre(a1);                                        \
        const float t2 = tanh_pre(a2);                                        \
        const bool lv = (T) < len;                                            \
        h0 = lv ? t0 : h0;                                                    \
        h1 = lv ? t1 : h1;                                                    \
        h2 = lv ? t2 : h2;                                                    \
    } while (0)
    #define S2(T)  STEP(T); STEP((T)+1)
    #define S8(T)  S2(T); S2((T)+2); S2((T)+4); S2((T)+6)

    S8(0); S2(8); S2(10); S2(12);
    asm volatile("cp.async.wait_group 2;" ::: "memory");
    S2(14); S8(16); S2(24); S2(26); S2(28);
    asm volatile("cp.async.wait_group 1;" ::: "memory");
    S2(30); S8(32); S2(40); S2(42); S2(44);
    asm volatile("cp.async.wait_group 0;" ::: "memory");
    S2(46); S8(48); S8(56);

    #undef S8
    #undef S2
    #undef STEP

    out[b * Hn + 0] = h0;
    out[b * Hn + 1] = h1;
    out[b * Hn + 2] = h2;
}

extern "C" void kernel_launch(void* const* d_in, const int* in_sizes, int n_in,
                              void* d_out, int out_size)
{
    const float* x    = (const float*)d_in[0];
    const void*  L    = d_in[1];
    const float* W_ih = (const float*)d_in[2];
    const float* W_hh = (const float*)d_in[3];
    const float* b_ih = (const float*)d_in[4];
    const float* b_hh = (const float*)d_in[5];
    float* out = (float*)d_out;

    // Launch order [nop, proj, rnn, nop] makes global launch #6 = k_proj,
    // which is where ncu's "-s 5 -c 1" capture lands -> first k_proj profile.
    k_nop<<<1, 32>>>();
    k_proj<<<8192, 256>>>(x, L, W_ih, b_ih, b_hh);
    k_rnn<<<Bn / 32, 32>>>(L, W_hh, out);
    k_nop<<<1, 32>>>();
}